// round 8
// baseline (speedup 1.0000x reference)
#include <cuda_runtime.h>
#include <cuda_fp16.h>
#include <cstdint>

static constexpr int Bn = 8, Tn = 1024, Cn = 768, Hn = 12, Dn = 64;
static constexpr int Mn = Bn * Tn;      // 8192
static constexpr int KT = Cn / 16;      // 48 k16 chunks
static constexpr int MT = Mn / 16;      // 512 m16 tiles
static constexpr int NTW = Cn / 8;      // 96 n8 tiles per weight matrix
static constexpr int BH = Bn * Hn;      // 96

// ---------------------------------------------------------------------------
// Scratch device globals
// ---------------------------------------------------------------------------
// A fragments (fp16 hi/lo): [mt][tk][lane] -> uint4 (a0..a3)
__device__ uint4 g_xfh[MT * KT * 32];
__device__ uint4 g_xfl[MT * KT * 32];
__device__ uint4 g_yfh[MT * KT * 32];
__device__ uint4 g_yfl[MT * KT * 32];
// Weights B-frags (single fp16): [mat][nt][tk][lane] -> uint2 {b0,b1}
__device__ uint2 g_wf[4 * NTW * KT * 32];
// Q A-frags (hi/lo, pre-scaled 1/8): [bh][mt(64)][dc(4)][lane]
__device__ uint4 g_qfh[BH * 64 * 4 * 32];
__device__ uint4 g_qfl[BH * 64 * 4 * 32];
// K B-frags (single): [bh][nt(128)][dc(4)][lane]
__device__ uint2 g_kf[BH * 128 * 4 * 32];
// V^T B-frags (single): [bh][dt(8)][kc(64)][lane]
__device__ uint2 g_vtf[BH * 8 * 64 * 32];

// ---------------------------------------------------------------------------
// Helpers
// ---------------------------------------------------------------------------
__device__ __forceinline__ uint32_t smem_u32(const void* p) {
    uint32_t a;
    asm("{ .reg .u64 t; cvta.to.shared.u64 t, %1; cvt.u32.u64 %0, t; }"
        : "=r"(a) : "l"(p));
    return a;
}
__device__ __forceinline__ void cp16(uint32_t dst, const void* src) {
    asm volatile("cp.async.ca.shared.global [%0], [%1], 16;\n" :: "r"(dst), "l"(src));
}
__device__ __forceinline__ void cp8(uint32_t dst, const void* src) {
    asm volatile("cp.async.ca.shared.global [%0], [%1], 8;\n" :: "r"(dst), "l"(src));
}
#define CP_COMMIT() asm volatile("cp.async.commit_group;\n" ::: "memory")
#define CP_WAIT2()  asm volatile("cp.async.wait_group 2;\n" ::: "memory")
#define CP_WAIT1()  asm volatile("cp.async.wait_group 1;\n" ::: "memory")

__device__ __forceinline__ void mma16816(float* d, const uint32_t* a,
                                         uint32_t b0, uint32_t b1) {
    asm volatile(
        "mma.sync.aligned.m16n8k16.row.col.f32.f16.f16.f32 "
        "{%0,%1,%2,%3}, {%4,%5,%6,%7}, {%8,%9}, {%0,%1,%2,%3};\n"
        : "+f"(d[0]), "+f"(d[1]), "+f"(d[2]), "+f"(d[3])
        : "r"(a[0]), "r"(a[1]), "r"(a[2]), "r"(a[3]), "r"(b0), "r"(b1));
}

__device__ __forceinline__ uint32_t packh(float x, float y) {
    __half2 h = __floats2half2_rn(x, y);
    return *reinterpret_cast<uint32_t*>(&h);
}
__device__ __forceinline__ void split2h(float x, float y, uint32_t& h, uint32_t& l) {
    __half hx = __float2half_rn(x), hy = __float2half_rn(y);
    h = ((uint32_t)__half_as_ushort(hy) << 16) | (uint32_t)__half_as_ushort(hx);
    l = packh(x - __half2float(hx), y - __half2float(hy));
}

// ---------------------------------------------------------------------------
// Combined input split: x -> A-frags (hi/lo); W -> single fp16 B-frags
// ---------------------------------------------------------------------------
static constexpr int ACT_BLKS = (MT * KT) / 8;          // 3072
static constexpr int W_BLKS   = (4 * NTW * KT) / 8;     // 2304

__global__ __launch_bounds__(256)
void split_xw_kernel(const float* __restrict__ X,
                     const float* __restrict__ Wq, const float* __restrict__ Wk,
                     const float* __restrict__ Wv, const float* __restrict__ Wp)
{
    int lane = threadIdx.x & 31;
    if (blockIdx.x < ACT_BLKS) {
        int w = (blockIdx.x * 256 + threadIdx.x) >> 5;
        int tm = w / KT, tk = w % KT;
        int row = tm * 16 + (lane >> 2);
        int kc  = tk * 16 + ((lane & 3) << 1);

        float2 v00 = *(const float2*)(X + (size_t)row * Cn + kc);
        float2 v10 = *(const float2*)(X + (size_t)(row + 8) * Cn + kc);
        float2 v01 = *(const float2*)(X + (size_t)row * Cn + kc + 8);
        float2 v11 = *(const float2*)(X + (size_t)(row + 8) * Cn + kc + 8);

        uint4 h, l;
        split2h(v00.x, v00.y, h.x, l.x);
        split2h(v10.x, v10.y, h.y, l.y);
        split2h(v01.x, v01.y, h.z, l.z);
        split2h(v11.x, v11.y, h.w, l.w);
        size_t o = (size_t)w * 32 + lane;
        g_xfh[o] = h;
        g_xfl[o] = l;
    } else {
        int w = ((blockIdx.x - ACT_BLKS) * 256 + threadIdx.x) >> 5;
        int mat = w / (NTW * KT);
        int rem = w % (NTW * KT);
        int tn = rem / KT, tk = rem % KT;

        const float* W;
        switch (mat) {
            case 0: W = Wq; break;
            case 1: W = Wk; break;
            case 2: W = Wv; break;
            default: W = Wp; break;
        }
        int n  = tn * 8 + (lane >> 2);
        int k0 = tk * 16 + ((lane & 3) << 1);

        uint2 o;
        o.x = packh(W[(size_t)k0 * Cn + n], W[(size_t)(k0 + 1) * Cn + n]);
        o.y = packh(W[(size_t)(k0 + 8) * Cn + n], W[(size_t)(k0 + 9) * Cn + n]);
        g_wf[(size_t)w * 32 + lane] = o;
    }
}

// ---------------------------------------------------------------------------
// fp16 (A-split) tensor-core GEMM: Out tile = A[128,768] @ W[768,128] + bias
// 256 threads (8 warps: 4m x 2n). 3-stage cp.async pipeline, 2 k16-chunks per
// stage (24KB/stage) -> half the barriers, 64-MMA runs between syncs.
// Chunk layout within stage (12KB each): A_hi [0,4K) A_lo [4K,8K) B [8K,12K).
// Epilogue modes: 0 = fp32 (+bias) to Out; 1 = Q A-frags; 2 = K B-frags;
//                 3 = V^T B-frags via smem fp16 transpose (136-half stride).
// ---------------------------------------------------------------------------
static constexpr int CHK_BYTES = 12288;
static constexpr int STG_BYTES = 2 * CHK_BYTES;       // 24KB
static constexpr int GEMM_SMEM = 3 * STG_BYTES;       // 72KB
static constexpr int N_ITER    = KT / 2;              // 24

__device__ __forceinline__ void gemm_mma_body(const uint4* __restrict__ Ah,
                                              const uint4* __restrict__ Al,
                                              const uint2* __restrict__ Wf,
                                              const float* __restrict__ bias,
                                              float* __restrict__ Out,
                                              int mode)
{
    extern __shared__ __align__(16) char smem[];
    const uint32_t sbase = smem_u32(smem);
    const int tid  = threadIdx.x;
    const int lane = tid & 31;
    const int wid  = tid >> 5;
    const int wm   = wid >> 1;
    const int wn   = wid & 1;

    const int mtBase = blockIdx.y * 8;
    const int ntBase = blockIdx.x * 16;
    const int cp_t   = wid;

    const uint4* srcAh = Ah + ((size_t)(mtBase + cp_t) * KT) * 32 + lane;
    const uint4* srcAl = Al + ((size_t)(mtBase + cp_t) * KT) * 32 + lane;
    const uint2* srcB0 = Wf + ((size_t)(ntBase + cp_t) * KT) * 32 + lane;
    const uint2* srcB1 = Wf + ((size_t)(ntBase + cp_t + 8) * KT) * 32 + lane;

    // per-chunk destination offsets (within a chunk's 12KB)
    const uint32_t dA0 = sbase + cp_t * 512 + lane * 16;
    const uint32_t dA1 = dA0 + 4096;
    const uint32_t dB0 = sbase + 8192 + cp_t * 256 + lane * 8;
    const uint32_t dB1 = dB0 + 2048;

    float d[2][8][4];
#pragma unroll
    for (int i = 0; i < 2; i++)
#pragma unroll
        for (int j = 0; j < 8; j++)
#pragma unroll
            for (int e = 0; e < 4; e++) d[i][j][e] = 0.f;

    auto issue = [&](int slot, int it) {
        uint32_t so = (uint32_t)slot * STG_BYTES;
        int tk = it * 2;
#pragma unroll
        for (int c = 0; c < 2; c++) {
            uint32_t co = so + (uint32_t)c * CHK_BYTES;
            cp16(dA0 + co, srcAh + (size_t)(tk + c) * 32);
            cp16(dA1 + co, srcAl + (size_t)(tk + c) * 32);
            cp8(dB0 + co, srcB0 + (size_t)(tk + c) * 32);
            cp8(dB1 + co, srcB1 + (size_t)(tk + c) * 32);
        }
    };

    issue(0, 0); CP_COMMIT();
    issue(1, 1); CP_COMMIT();

    for (int it = 0; it < N_ITER; it++) {
        CP_WAIT1();
        __syncthreads();
        if (it + 2 < N_ITER) issue((it + 2) % 3, it + 2);
        CP_COMMIT();

        const char* stg0 = smem + (size_t)(it % 3) * STG_BYTES;
#pragma unroll
        for (int c = 0; c < 2; c++) {
            const char* stg = stg0 + c * CHK_BYTES;
            uint4 ah0 = *(const uint4*)(stg + (wm * 2 + 0) * 512 + lane * 16);
            uint4 ah1 = *(const uint4*)(stg + (wm * 2 + 1) * 512 + lane * 16);
            uint4 al0 = *(const uint4*)(stg + 4096 + (wm * 2 + 0) * 512 + lane * 16);
            uint4 al1 = *(const uint4*)(stg + 4096 + (wm * 2 + 1) * 512 + lane * 16);
#pragma unroll
            for (int nt = 0; nt < 8; nt++) {
                uint2 b = *(const uint2*)(stg + 8192 + (wn * 8 + nt) * 256 + lane * 8);
                mma16816(d[0][nt], (const uint32_t*)&ah0, b.x, b.y);
                mma16816(d[0][nt], (const uint32_t*)&al0, b.x, b.y);
                mma16816(d[1][nt], (const uint32_t*)&ah1, b.x, b.y);
                mma16816(d[1][nt], (const uint32_t*)&al1, b.x, b.y);
            }
        }
    }

    const int cb = blockIdx.x * 128 + wn * 64 + ((lane & 3) << 1);
    const int h  = blockIdx.x * 2 + wn;

    if (mode == 3) {
        // V^T fragments via smem fp16 transpose (row stride 136 halves).
        __syncthreads();
        __half* sv = reinterpret_cast<__half*>(smem);
#pragma unroll
        for (int mt = 0; mt < 2; mt++) {
            int r = wm * 32 + mt * 16 + (lane >> 2);
#pragma unroll
            for (int nt = 0; nt < 8; nt++) {
                int cl  = wn * 64 + nt * 8 + ((lane & 3) << 1);
                int col = blockIdx.x * 128 + cl;
                float bx = bias[col], by = bias[col + 1];
                *(__half2*)&sv[r * 136 + cl] =
                    __floats2half2_rn(d[mt][nt][0] + bx, d[mt][nt][1] + by);
                *(__half2*)&sv[(r + 8) * 136 + cl] =
                    __floats2half2_rn(d[mt][nt][2] + bx, d[mt][nt][3] + by);
            }
        }
        __syncthreads();
        const ushort* su = reinterpret_cast<const ushort*>(sv);
        const int bb  = blockIdx.y >> 3;
        const int kcb = (blockIdx.y & 7) * 8;
        const int dt  = wid;
#pragma unroll
        for (int hh = 0; hh < 2; hh++) {
            int dl  = hh * 64 + dt * 8 + (lane >> 2);
            int bh2 = bb * Hn + blockIdx.x * 2 + hh;
#pragma unroll
            for (int kl = 0; kl < 8; kl++) {
                int k0 = kl * 16 + ((lane & 3) << 1);
                uint2 o;
                o.x = (uint32_t)su[k0 * 136 + dl] |
                      ((uint32_t)su[(k0 + 1) * 136 + dl] << 16);
                o.y = (uint32_t)su[(k0 + 8) * 136 + dl] |
                      ((uint32_t)su[(k0 + 9) * 136 + dl] << 16);
                g_vtf[(((size_t)bh2 * 8 + dt) * 64 + kcb + kl) * 32 + lane] = o;
            }
        }
        return;
    }

#pragma unroll
    for (int mt = 0; mt < 2; mt++) {
        const int rg = blockIdx.y * 128 + wm * 32 + mt * 16;
        if (mode == 0) {
            const int r0 = rg + (lane >> 2);
#pragma unroll
            for (int nt = 0; nt < 8; nt++) {
                int col = cb + nt * 8;
                float bx = bias[col], by = bias[col + 1];
                *(float2*)(Out + (size_t)r0 * Cn + col) =
                    make_float2(d[mt][nt][0] + bx, d[mt][nt][1] + by);
                *(float2*)(Out + (size_t)(r0 + 8) * Cn + col) =
                    make_float2(d[mt][nt][2] + bx, d[mt][nt][3] + by);
            }
        } else if (mode == 1) {
            // Q A-fragments: scale 1/8, bias folded
            const int bq_ = rg >> 10;
            const int mtq = (rg & 1023) >> 4;
            const size_t base =
                ((size_t)((bq_ * Hn + h) * 64 + mtq) * 4) * 32 + lane;
#pragma unroll
            for (int dc = 0; dc < 4; dc++) {
                int c0 = cb + (2 * dc) * 8, c1 = cb + (2 * dc + 1) * 8;
                float b00 = bias[c0], b01 = bias[c0 + 1];
                float b10 = bias[c1], b11 = bias[c1 + 1];
                uint4 hh, ll;
                split2h((d[mt][2*dc][0]   + b00) * 0.125f,
                        (d[mt][2*dc][1]   + b01) * 0.125f, hh.x, ll.x);
                split2h((d[mt][2*dc][2]   + b00) * 0.125f,
                        (d[mt][2*dc][3]   + b01) * 0.125f, hh.y, ll.y);
                split2h((d[mt][2*dc+1][0] + b10) * 0.125f,
                        (d[mt][2*dc+1][1] + b11) * 0.125f, hh.z, ll.z);
                split2h((d[mt][2*dc+1][2] + b10) * 0.125f,
                        (d[mt][2*dc+1][3] + b11) * 0.125f, hh.w, ll.w);
                g_qfh[base + dc * 32] = hh;
                g_qfl[base + dc * 32] = ll;
            }
        } else {
            // K B-fragments (single fp16): two n8 key-tiles per m16
            const int bq_ = rg >> 10;
            const int ntk = (rg & 1023) >> 3;
            const size_t base =
                ((size_t)((bq_ * Hn + h) * 128 + ntk) * 4) * 32 + lane;
#pragma unroll
            for (int dc = 0; dc < 4; dc++) {
                int c0 = cb + (2 * dc) * 8, c1 = cb + (2 * dc + 1) * 8;
                float b00 = bias[c0], b01 = bias[c0 + 1];
                float b10 = bias[c1], b11 = bias[c1 + 1];
                uint2 t0, t1;
                t0.x = packh(d[mt][2*dc][0]   + b00, d[mt][2*dc][1]   + b01);
                t0.y = packh(d[mt][2*dc+1][0] + b10, d[mt][2*dc+1][1] + b11);
                t1.x = packh(d[mt][2*dc][2]   + b00, d[mt][2*dc][3]   + b01);
                t1.y = packh(d[mt][2*dc+1][2] + b10, d[mt][2*dc+1][3] + b11);
                g_kf[base + dc * 32]          = t0;
                g_kf[base + 4 * 32 + dc * 32] = t1;
            }
        }
    }
}

__global__ __launch_bounds__(256, 1)
void qkv_mma(const float* __restrict__ bq, const float* __restrict__ bk,
             const float* __restrict__ bv)
{
    const uint2* Wf = g_wf + (size_t)blockIdx.z * NTW * KT * 32;
    if (blockIdx.z == 0)      gemm_mma_body(g_xfh, g_xfl, Wf, bq, nullptr, 1);
    else if (blockIdx.z == 1) gemm_mma_body(g_xfh, g_xfl, Wf, bk, nullptr, 2);
    else                      gemm_mma_body(g_xfh, g_xfl, Wf, bv, nullptr, 3);
}

__global__ __launch_bounds__(256, 1)
void proj_mma(const float* __restrict__ bp, float* __restrict__ out)
{
    gemm_mma_body(g_yfh, g_yfl, g_wf + (size_t)3 * NTW * KT * 32, bp, out, 0);
}

// ---------------------------------------------------------------------------
// fp16 tensor-core flash attention (unchanged from R6).
// Block = (64 q-rows, head, batch), 128 threads = 4 warps (m16 each).
// CTA order reversed so the longest q-tiles launch first.
// ---------------------------------------------------------------------------
static constexpr int ATT_STG  = 16384;
static constexpr int ATT_SMEM = 3 * ATT_STG;   // 48KB

__global__ __launch_bounds__(128, 1)
void attn_mma()
{
    extern __shared__ __align__(16) char smem[];
    const uint32_t sbase = smem_u32(smem);
    const int tid  = threadIdx.x;
    const int lane = tid & 31;
    const int w    = tid >> 5;
    const int qt   = gridDim.x - 1 - blockIdx.x;
    const int h    = blockIdx.y;
    const int b    = blockIdx.z;
    const int bh   = b * Hn + h;
    const int nkt  = qt + 1;

    uint4 qh[4], ql[4];
    {
        const uint4* Qh = g_qfh + ((size_t)(bh * 64 + qt * 4 + w) * 4) * 32 + lane;
        const uint4* Ql = g_qfl + ((size_t)(bh * 64 + qt * 4 + w) * 4) * 32 + lane;
#pragma unroll
        for (int dc = 0; dc < 4; dc++) { qh[dc] = Qh[dc * 32]; ql[dc] = Ql[dc * 32]; }
    }

    float o[8][4];
#pragma unroll
    for (int i = 0; i < 8; i++)
#pragma unroll
        for (int j = 0; j < 4; j++) o[i][j] = 0.f;
    float m[2] = {-1e30f, -1e30f}, l[2] = {0.f, 0.f};

    const uint2* Ksrc = g_kf  + (size_t)bh * 128 * 4 * 32;
    const uint2* Vsrc = g_vtf + (size_t)bh * 8 * 64 * 32;
    const int vkc = w;

    auto issue = [&](int slot, int kt) {
        uint32_t so = sbase + (uint32_t)slot * ATT_STG;
        const uint2* ks = Ksrc + (size_t)kt * 1024;
#pragma unroll
        for (int i = 0; i < 8; i++)
            cp8(so + (uint32_t)(i * 128 + tid) * 8, ks + i * 128 + tid);
#pragma unroll
        for (int dt = 0; dt < 8; dt++)
            cp8(so + 8192 + (uint32_t)((dt * 4 + vkc) * 32 + lane) * 8,
                Vsrc + ((size_t)dt * 64 + kt * 4 + vkc) * 32 + lane);
    };

    issue(0, 0); CP_COMMIT();
    if (nkt > 1) issue(1, 1);
    CP_COMMIT();

    for (int kt = 0; kt < nkt; kt++) {
        CP_WAIT1();
        __syncthreads();
        if (kt + 2 < nkt) issue((kt + 2) % 3, kt + 2);
        CP_COMMIT();

        const char* stK = smem + (size_t)(kt % 3) * ATT_STG;
        const char* stV = stK + 8192;

        // S = Q @ K^T (Q split hi/lo, K single)
        float s[8][4];
#pragma unroll
        for (int i = 0; i < 8; i++)
#pragma unroll
            for (int j = 0; j < 4; j++) s[i][j] = 0.f;
#pragma unroll
        for (int dc = 0; dc < 4; dc++) {
#pragma unroll
            for (int nt = 0; nt < 8; nt++) {
                uint2 kb = *(const uint2*)(stK + ((nt * 4 + dc) * 32 + lane) * 8);
                mma16816(s[nt], (const uint32_t*)&qh[dc], kb.x, kb.y);
                mma16816(s[nt], (const uint32_t*)&ql[dc], kb.x, kb.y);
            }
        }

        // Causal mask (diagonal tile only)
        if (kt == qt) {
            int r0 = w * 16 + (lane >> 2);
            int c0 = (lane & 3) << 1;
#pragma unroll
            for (int nt = 0; nt < 8; nt++) {
                int col = nt * 8 + c0;
                if (col > r0)         s[nt][0] = -1e30f;
                if (col + 1 > r0)     s[nt][1] = -1e30f;
                if (col > r0 + 8)     s[nt][2] = -1e30f;
                if (col + 1 > r0 + 8) s[nt][3] = -1e30f;
            }
        }

        // Online softmax per row-half
#pragma unroll
        for (int i = 0; i < 2; i++) {
            float tm = -1e30f;
#pragma unroll
            for (int nt = 0; nt < 8; nt++)
                tm = fmaxf(tm, fmaxf(s[nt][2 * i], s[nt][2 * i + 1]));
            tm = fmaxf(tm, __shfl_xor_sync(0xffffffffu, tm, 1));
            tm = fmaxf(tm, __shfl_xor_sync(0xffffffffu, tm, 2));
            float newm = fmaxf(m[i], tm);
            float fac  = __expf(m[i] - newm);
            m[i] = newm;
            float rs = 0.f;
#pragma unroll
            for (int nt = 0; nt < 8; nt++) {
                float p0 = __expf(s[nt][2 * i] - newm);
                float p1 = __expf(s[nt][2 * i + 1] - newm);
                s[nt][2 * i] = p0;
                s[nt][2 * i + 1] = p1;
                rs += p0 + p1;
            }
            rs += __shfl_xor_sync(0xffffffffu, rs, 1);
            rs += __shfl_xor_sync(0xffffffffu, rs, 2);
            l[i] = l[i] * fac + rs;
#pragma unroll
            for (int dt = 0; dt < 8; dt++) {
                o[dt][2 * i]     *= fac;
                o[dt][2 * i + 1] *= fac;
            }
        }

        // O += P @ V  (P single fp16)
#pragma unroll
        for (int t = 0; t < 4; t++) {
            uint32_t ph[4];
            ph[0] = packh(s[2*t][0],   s[2*t][1]);
            ph[1] = packh(s[2*t][2],   s[2*t][3]);
            ph[2] = packh(s[2*t+1][0], s[2*t+1][1]);
            ph[3] = packh(s[2*t+1][2], s[2*t+1][3]);
#pragma unroll
            for (int dt = 0; dt < 8; dt++) {
                uint2 v = *(const uint2*)(stV + ((dt * 4 + t) * 32 + lane) * 8);
                mma16816(o[dt], ph, v.x, v.y);
            }
        }
    }

    // Epilogue: normalize, write y A-fragments (hi/lo) for proj GEMM
    const float inv0 = 1.f / l[0];
    const float inv1 = 1.f / l[1];
    const int mtg = b * 64 + qt * 4 + w;
#pragma unroll
    for (int dtc = 0; dtc < 4; dtc++) {
        uint4 hh, ll;
        split2h(o[2*dtc][0]   * inv0, o[2*dtc][1]   * inv0, hh.x, ll.x);
        split2h(o[2*dtc][2]   * inv1, o[2*dtc][3]   * inv1, hh.y, ll.y);
        split2h(o[2*dtc+1][0] * inv0, o[2*dtc+1][1] * inv0, hh.z, ll.z);
        split2h(o[2*dtc+1][2] * inv1, o[2*dtc+1][3] * inv1, hh.w, ll.w);
        size_t idx = ((size_t)mtg * KT + h * 4 + dtc) * 32 + lane;
        g_yfh[idx] = hh;
        g_yfl[idx] = ll;
    }
}

// ---------------------------------------------------------------------------
extern "C" void kernel_launch(void* const* d_in, const int* in_sizes, int n_in,
                              void* d_out, int out_size)
{
    const float* x  = (const float*)d_in[0];
    const float* Wq = (const float*)d_in[1];
    const float* bq = (const float*)d_in[2];
    const float* Wk = (const float*)d_in[3];
    const float* bk = (const float*)d_in[4];
    const float* Wv = (const float*)d_in[5];
    const float* bv = (const float*)d_in[6];
    const float* Wp = (const float*)d_in[7];
    const float* bp = (const float*)d_in[8];
    float* out = (float*)d_out;

    cudaFuncSetAttribute(qkv_mma, cudaFuncAttributeMaxDynamicSharedMemorySize, GEMM_SMEM);
    cudaFuncSetAttribute(proj_mma, cudaFuncAttributeMaxDynamicSharedMemorySize, GEMM_SMEM);
    cudaFuncSetAttribute(attn_mma, cudaFuncAttributeMaxDynamicSharedMemorySize, ATT_SMEM);

    split_xw_kernel<<<ACT_BLKS + W_BLKS, 256>>>(x, Wq, Wk, Wv, Wp);
    qkv_mma<<<dim3(Cn / 128, Mn / 128, 3), 256, GEMM_SMEM>>>(bq, bk, bv);
    attn_mma<<<dim3(Tn / 64, Hn, Bn), 128, ATT_SMEM>>>();
    proj_mma<<<dim3(Cn / 128, Mn / 128, 1), 256, GEMM_SMEM>>>(bp, out);
}

// round 9
// speedup vs baseline: 1.2826x; 1.2826x over previous
#include <cuda_runtime.h>
#include <cuda_fp16.h>
#include <cstdint>

static constexpr int Bn = 8, Tn = 1024, Cn = 768, Hn = 12, Dn = 64;
static constexpr int Mn = Bn * Tn;      // 8192
static constexpr int KT = Cn / 16;      // 48 k16 chunks
static constexpr int MT = Mn / 16;      // 512 m16 tiles
static constexpr int NTW = Cn / 8;      // 96 n8 tiles per weight matrix
static constexpr int BH = Bn * Hn;      // 96

// ---------------------------------------------------------------------------
// Scratch device globals
// ---------------------------------------------------------------------------
// A fragments (fp16 hi/lo): [mt][tk][lane] -> uint4 (a0..a3)
__device__ uint4 g_xfh[MT * KT * 32];
__device__ uint4 g_xfl[MT * KT * 32];
__device__ uint4 g_yfh[MT * KT * 32];   // y single-rounded fp16 (no lo)
// Weights B-frags (single fp16): [mat][nt][tk][lane] -> uint2 {b0,b1}
__device__ uint2 g_wf[4 * NTW * KT * 32];
// Q A-frags (hi/lo, pre-scaled 1/8): [bh][mt(64)][dc(4)][lane]
__device__ uint4 g_qfh[BH * 64 * 4 * 32];
__device__ uint4 g_qfl[BH * 64 * 4 * 32];
// K B-frags (single): [bh][nt(128)][dc(4)][lane]
__device__ uint2 g_kf[BH * 128 * 4 * 32];
// V^T B-frags (single): [bh][dt(8)][kc(64)][lane]
__device__ uint2 g_vtf[BH * 8 * 64 * 32];

// ---------------------------------------------------------------------------
// Helpers
// ---------------------------------------------------------------------------
__device__ __forceinline__ uint32_t smem_u32(const void* p) {
    uint32_t a;
    asm("{ .reg .u64 t; cvta.to.shared.u64 t, %1; cvt.u32.u64 %0, t; }"
        : "=r"(a) : "l"(p));
    return a;
}
__device__ __forceinline__ void cp16(uint32_t dst, const void* src) {
    asm volatile("cp.async.ca.shared.global [%0], [%1], 16;\n" :: "r"(dst), "l"(src));
}
__device__ __forceinline__ void cp8(uint32_t dst, const void* src) {
    asm volatile("cp.async.ca.shared.global [%0], [%1], 8;\n" :: "r"(dst), "l"(src));
}
#define CP_COMMIT() asm volatile("cp.async.commit_group;\n" ::: "memory")
#define CP_WAIT2()  asm volatile("cp.async.wait_group 2;\n" ::: "memory")
#define CP_WAIT1()  asm volatile("cp.async.wait_group 1;\n" ::: "memory")

__device__ __forceinline__ void mma16816(float* d, const uint32_t* a,
                                         uint32_t b0, uint32_t b1) {
    asm volatile(
        "mma.sync.aligned.m16n8k16.row.col.f32.f16.f16.f32 "
        "{%0,%1,%2,%3}, {%4,%5,%6,%7}, {%8,%9}, {%0,%1,%2,%3};\n"
        : "+f"(d[0]), "+f"(d[1]), "+f"(d[2]), "+f"(d[3])
        : "r"(a[0]), "r"(a[1]), "r"(a[2]), "r"(a[3]), "r"(b0), "r"(b1));
}

__device__ __forceinline__ uint32_t packh(float x, float y) {
    __half2 h = __floats2half2_rn(x, y);
    return *reinterpret_cast<uint32_t*>(&h);
}
__device__ __forceinline__ void split2h(float x, float y, uint32_t& h, uint32_t& l) {
    __half hx = __float2half_rn(x), hy = __float2half_rn(y);
    h = ((uint32_t)__half_as_ushort(hy) << 16) | (uint32_t)__half_as_ushort(hx);
    l = packh(x - __half2float(hx), y - __half2float(hy));
}

// ---------------------------------------------------------------------------
// Combined input split: x -> A-frags (hi/lo); W -> single fp16 B-frags
// ---------------------------------------------------------------------------
static constexpr int ACT_BLKS = (MT * KT) / 8;          // 3072
static constexpr int W_BLKS   = (4 * NTW * KT) / 8;     // 2304

__global__ __launch_bounds__(256)
void split_xw_kernel(const float* __restrict__ X,
                     const float* __restrict__ Wq, const float* __restrict__ Wk,
                     const float* __restrict__ Wv, const float* __restrict__ Wp)
{
    int lane = threadIdx.x & 31;
    if (blockIdx.x < ACT_BLKS) {
        int w = (blockIdx.x * 256 + threadIdx.x) >> 5;
        int tm = w / KT, tk = w % KT;
        int row = tm * 16 + (lane >> 2);
        int kc  = tk * 16 + ((lane & 3) << 1);

        float2 v00 = *(const float2*)(X + (size_t)row * Cn + kc);
        float2 v10 = *(const float2*)(X + (size_t)(row + 8) * Cn + kc);
        float2 v01 = *(const float2*)(X + (size_t)row * Cn + kc + 8);
        float2 v11 = *(const float2*)(X + (size_t)(row + 8) * Cn + kc + 8);

        uint4 h, l;
        split2h(v00.x, v00.y, h.x, l.x);
        split2h(v10.x, v10.y, h.y, l.y);
        split2h(v01.x, v01.y, h.z, l.z);
        split2h(v11.x, v11.y, h.w, l.w);
        size_t o = (size_t)w * 32 + lane;
        g_xfh[o] = h;
        g_xfl[o] = l;
    } else {
        int w = ((blockIdx.x - ACT_BLKS) * 256 + threadIdx.x) >> 5;
        int mat = w / (NTW * KT);
        int rem = w % (NTW * KT);
        int tn = rem / KT, tk = rem % KT;

        const float* W;
        switch (mat) {
            case 0: W = Wq; break;
            case 1: W = Wk; break;
            case 2: W = Wv; break;
            default: W = Wp; break;
        }
        int n  = tn * 8 + (lane >> 2);
        int k0 = tk * 16 + ((lane & 3) << 1);

        uint2 o;
        o.x = packh(W[(size_t)k0 * Cn + n], W[(size_t)(k0 + 1) * Cn + n]);
        o.y = packh(W[(size_t)(k0 + 8) * Cn + n], W[(size_t)(k0 + 9) * Cn + n]);
        g_wf[(size_t)w * 32 + lane] = o;
    }
}

// ---------------------------------------------------------------------------
// fp16 tensor-core GEMM (R6 structure). DUAL: A split hi/lo (2 MMAs per step);
// !DUAL: single A (1 MMA per step) — used for proj where y is single fp16.
// 256 threads (8 warps: 4m x 2n). 4-stage cp.async pipeline, 12KB/stage.
// Epilogue modes: 0 = fp32 (+bias) to Out; 1 = Q A-frags; 2 = K B-frags;
//                 3 = V^T B-frags via smem fp16 transpose (136-half stride).
// ---------------------------------------------------------------------------
static constexpr int STG_BYTES = 12288;
static constexpr int GEMM_SMEM = 4 * STG_BYTES;   // 48KB

template <bool DUAL>
__device__ __forceinline__ void gemm_mma_body(const uint4* __restrict__ Ah,
                                              const uint4* __restrict__ Al,
                                              const uint2* __restrict__ Wf,
                                              const float* __restrict__ bias,
                                              float* __restrict__ Out,
                                              int mode)
{
    extern __shared__ __align__(16) char smem[];
    const uint32_t sbase = smem_u32(smem);
    const int tid  = threadIdx.x;
    const int lane = tid & 31;
    const int wid  = tid >> 5;
    const int wm   = wid >> 1;
    const int wn   = wid & 1;

    const int mtBase = blockIdx.y * 8;
    const int ntBase = blockIdx.x * 16;
    const int cp_t   = wid;

    const uint4* srcAh = Ah + ((size_t)(mtBase + cp_t) * KT) * 32 + lane;
    const uint4* srcAl = DUAL ? Al + ((size_t)(mtBase + cp_t) * KT) * 32 + lane
                              : nullptr;
    const uint2* srcB0 = Wf + ((size_t)(ntBase + cp_t) * KT) * 32 + lane;
    const uint2* srcB1 = Wf + ((size_t)(ntBase + cp_t + 8) * KT) * 32 + lane;

    const uint32_t dA0 = sbase + cp_t * 512 + lane * 16;
    const uint32_t dA1 = dA0 + 4096;
    const uint32_t dB0 = sbase + 8192 + cp_t * 256 + lane * 8;
    const uint32_t dB1 = dB0 + 2048;

    float d[2][8][4];
#pragma unroll
    for (int i = 0; i < 2; i++)
#pragma unroll
        for (int j = 0; j < 8; j++)
#pragma unroll
            for (int e = 0; e < 4; e++) d[i][j][e] = 0.f;

    auto issue = [&](int slot, int tk) {
        uint32_t so = (uint32_t)slot * STG_BYTES;
        cp16(dA0 + so, srcAh + (size_t)tk * 32);
        if (DUAL) cp16(dA1 + so, srcAl + (size_t)tk * 32);
        cp8(dB0 + so, srcB0 + (size_t)tk * 32);
        cp8(dB1 + so, srcB1 + (size_t)tk * 32);
    };

    issue(0, 0); CP_COMMIT();
    issue(1, 1); CP_COMMIT();
    issue(2, 2); CP_COMMIT();

    for (int k = 0; k < KT; k++) {
        CP_WAIT2();
        __syncthreads();
        if (k + 3 < KT) issue((k + 3) & 3, k + 3);
        CP_COMMIT();

        const char* stg = smem + (size_t)(k & 3) * STG_BYTES;
        uint4 ah0 = *(const uint4*)(stg + (wm * 2 + 0) * 512 + lane * 16);
        uint4 ah1 = *(const uint4*)(stg + (wm * 2 + 1) * 512 + lane * 16);
        uint4 al0, al1;
        if (DUAL) {
            al0 = *(const uint4*)(stg + 4096 + (wm * 2 + 0) * 512 + lane * 16);
            al1 = *(const uint4*)(stg + 4096 + (wm * 2 + 1) * 512 + lane * 16);
        }
#pragma unroll
        for (int nt = 0; nt < 8; nt++) {
            uint2 b = *(const uint2*)(stg + 8192 + (wn * 8 + nt) * 256 + lane * 8);
            mma16816(d[0][nt], (const uint32_t*)&ah0, b.x, b.y);
            if (DUAL) mma16816(d[0][nt], (const uint32_t*)&al0, b.x, b.y);
            mma16816(d[1][nt], (const uint32_t*)&ah1, b.x, b.y);
            if (DUAL) mma16816(d[1][nt], (const uint32_t*)&al1, b.x, b.y);
        }
    }

    const int cb = blockIdx.x * 128 + wn * 64 + ((lane & 3) << 1);
    const int h  = blockIdx.x * 2 + wn;

    if (mode == 3) {
        // V^T fragments via smem fp16 transpose (row stride 136 halves).
        __syncthreads();
        __half* sv = reinterpret_cast<__half*>(smem);
#pragma unroll
        for (int mt = 0; mt < 2; mt++) {
            int r = wm * 32 + mt * 16 + (lane >> 2);
#pragma unroll
            for (int nt = 0; nt < 8; nt++) {
                int cl  = wn * 64 + nt * 8 + ((lane & 3) << 1);
                int col = blockIdx.x * 128 + cl;
                float bx = bias[col], by = bias[col + 1];
                *(__half2*)&sv[r * 136 + cl] =
                    __floats2half2_rn(d[mt][nt][0] + bx, d[mt][nt][1] + by);
                *(__half2*)&sv[(r + 8) * 136 + cl] =
                    __floats2half2_rn(d[mt][nt][2] + bx, d[mt][nt][3] + by);
            }
        }
        __syncthreads();
        const ushort* su = reinterpret_cast<const ushort*>(sv);
        const int bb  = blockIdx.y >> 3;
        const int kcb = (blockIdx.y & 7) * 8;
        const int dt  = wid;
#pragma unroll
        for (int hh = 0; hh < 2; hh++) {
            int dl  = hh * 64 + dt * 8 + (lane >> 2);
            int bh2 = bb * Hn + blockIdx.x * 2 + hh;
#pragma unroll
            for (int kl = 0; kl < 8; kl++) {
                int k0 = kl * 16 + ((lane & 3) << 1);
                uint2 o;
                o.x = (uint32_t)su[k0 * 136 + dl] |
                      ((uint32_t)su[(k0 + 1) * 136 + dl] << 16);
                o.y = (uint32_t)su[(k0 + 8) * 136 + dl] |
                      ((uint32_t)su[(k0 + 9) * 136 + dl] << 16);
                g_vtf[(((size_t)bh2 * 8 + dt) * 64 + kcb + kl) * 32 + lane] = o;
            }
        }
        return;
    }

#pragma unroll
    for (int mt = 0; mt < 2; mt++) {
        const int rg = blockIdx.y * 128 + wm * 32 + mt * 16;
        if (mode == 0) {
            const int r0 = rg + (lane >> 2);
#pragma unroll
            for (int nt = 0; nt < 8; nt++) {
                int col = cb + nt * 8;
                float bx = bias[col], by = bias[col + 1];
                *(float2*)(Out + (size_t)r0 * Cn + col) =
                    make_float2(d[mt][nt][0] + bx, d[mt][nt][1] + by);
                *(float2*)(Out + (size_t)(r0 + 8) * Cn + col) =
                    make_float2(d[mt][nt][2] + bx, d[mt][nt][3] + by);
            }
        } else if (mode == 1) {
            // Q A-fragments: scale 1/8, bias folded
            const int bq_ = rg >> 10;
            const int mtq = (rg & 1023) >> 4;
            const size_t base =
                ((size_t)((bq_ * Hn + h) * 64 + mtq) * 4) * 32 + lane;
#pragma unroll
            for (int dc = 0; dc < 4; dc++) {
                int c0 = cb + (2 * dc) * 8, c1 = cb + (2 * dc + 1) * 8;
                float b00 = bias[c0], b01 = bias[c0 + 1];
                float b10 = bias[c1], b11 = bias[c1 + 1];
                uint4 hh, ll;
                split2h((d[mt][2*dc][0]   + b00) * 0.125f,
                        (d[mt][2*dc][1]   + b01) * 0.125f, hh.x, ll.x);
                split2h((d[mt][2*dc][2]   + b00) * 0.125f,
                        (d[mt][2*dc][3]   + b01) * 0.125f, hh.y, ll.y);
                split2h((d[mt][2*dc+1][0] + b10) * 0.125f,
                        (d[mt][2*dc+1][1] + b11) * 0.125f, hh.z, ll.z);
                split2h((d[mt][2*dc+1][2] + b10) * 0.125f,
                        (d[mt][2*dc+1][3] + b11) * 0.125f, hh.w, ll.w);
                g_qfh[base + dc * 32] = hh;
                g_qfl[base + dc * 32] = ll;
            }
        } else {
            // K B-fragments (single fp16): two n8 key-tiles per m16
            const int bq_ = rg >> 10;
            const int ntk = (rg & 1023) >> 3;
            const size_t base =
                ((size_t)((bq_ * Hn + h) * 128 + ntk) * 4) * 32 + lane;
#pragma unroll
            for (int dc = 0; dc < 4; dc++) {
                int c0 = cb + (2 * dc) * 8, c1 = cb + (2 * dc + 1) * 8;
                float b00 = bias[c0], b01 = bias[c0 + 1];
                float b10 = bias[c1], b11 = bias[c1 + 1];
                uint2 t0, t1;
                t0.x = packh(d[mt][2*dc][0]   + b00, d[mt][2*dc][1]   + b01);
                t0.y = packh(d[mt][2*dc+1][0] + b10, d[mt][2*dc+1][1] + b11);
                t1.x = packh(d[mt][2*dc][2]   + b00, d[mt][2*dc][3]   + b01);
                t1.y = packh(d[mt][2*dc+1][2] + b10, d[mt][2*dc+1][3] + b11);
                g_kf[base + dc * 32]          = t0;
                g_kf[base + 4 * 32 + dc * 32] = t1;
            }
        }
    }
}

__global__ __launch_bounds__(256, 1)
void qkv_mma(const float* __restrict__ bq, const float* __restrict__ bk,
             const float* __restrict__ bv)
{
    const uint2* Wf = g_wf + (size_t)blockIdx.z * NTW * KT * 32;
    if (blockIdx.z == 0)      gemm_mma_body<true>(g_xfh, g_xfl, Wf, bq, nullptr, 1);
    else if (blockIdx.z == 1) gemm_mma_body<true>(g_xfh, g_xfl, Wf, bk, nullptr, 2);
    else                      gemm_mma_body<true>(g_xfh, g_xfl, Wf, bv, nullptr, 3);
}

__global__ __launch_bounds__(256, 1)
void proj_mma(const float* __restrict__ bp, float* __restrict__ out)
{
    gemm_mma_body<false>(g_yfh, nullptr, g_wf + (size_t)3 * NTW * KT * 32,
                         bp, out, 0);
}

// ---------------------------------------------------------------------------
// fp16 tensor-core flash attention (R6 structure; epilogue writes single
// fp16 y fragments — no lo residual).
// Block = (64 q-rows, head, batch), 128 threads = 4 warps (m16 each).
// CTA order reversed so the longest q-tiles launch first.
// ---------------------------------------------------------------------------
static constexpr int ATT_STG  = 16384;
static constexpr int ATT_SMEM = 3 * ATT_STG;   // 48KB

__global__ __launch_bounds__(128, 1)
void attn_mma()
{
    extern __shared__ __align__(16) char smem[];
    const uint32_t sbase = smem_u32(smem);
    const int tid  = threadIdx.x;
    const int lane = tid & 31;
    const int w    = tid >> 5;
    const int qt   = gridDim.x - 1 - blockIdx.x;
    const int h    = blockIdx.y;
    const int b    = blockIdx.z;
    const int bh   = b * Hn + h;
    const int nkt  = qt + 1;

    uint4 qh[4], ql[4];
    {
        const uint4* Qh = g_qfh + ((size_t)(bh * 64 + qt * 4 + w) * 4) * 32 + lane;
        const uint4* Ql = g_qfl + ((size_t)(bh * 64 + qt * 4 + w) * 4) * 32 + lane;
#pragma unroll
        for (int dc = 0; dc < 4; dc++) { qh[dc] = Qh[dc * 32]; ql[dc] = Ql[dc * 32]; }
    }

    float o[8][4];
#pragma unroll
    for (int i = 0; i < 8; i++)
#pragma unroll
        for (int j = 0; j < 4; j++) o[i][j] = 0.f;
    float m[2] = {-1e30f, -1e30f}, l[2] = {0.f, 0.f};

    const uint2* Ksrc = g_kf  + (size_t)bh * 128 * 4 * 32;
    const uint2* Vsrc = g_vtf + (size_t)bh * 8 * 64 * 32;
    const int vkc = w;

    auto issue = [&](int slot, int kt) {
        uint32_t so = sbase + (uint32_t)slot * ATT_STG;
        const uint2* ks = Ksrc + (size_t)kt * 1024;
#pragma unroll
        for (int i = 0; i < 8; i++)
            cp8(so + (uint32_t)(i * 128 + tid) * 8, ks + i * 128 + tid);
#pragma unroll
        for (int dt = 0; dt < 8; dt++)
            cp8(so + 8192 + (uint32_t)((dt * 4 + vkc) * 32 + lane) * 8,
                Vsrc + ((size_t)dt * 64 + kt * 4 + vkc) * 32 + lane);
    };

    issue(0, 0); CP_COMMIT();
    if (nkt > 1) issue(1, 1);
    CP_COMMIT();

    for (int kt = 0; kt < nkt; kt++) {
        CP_WAIT1();
        __syncthreads();
        if (kt + 2 < nkt) issue((kt + 2) % 3, kt + 2);
        CP_COMMIT();

        const char* stK = smem + (size_t)(kt % 3) * ATT_STG;
        const char* stV = stK + 8192;

        // S = Q @ K^T (Q split hi/lo, K single)
        float s[8][4];
#pragma unroll
        for (int i = 0; i < 8; i++)
#pragma unroll
            for (int j = 0; j < 4; j++) s[i][j] = 0.f;
#pragma unroll
        for (int dc = 0; dc < 4; dc++) {
#pragma unroll
            for (int nt = 0; nt < 8; nt++) {
                uint2 kb = *(const uint2*)(stK + ((nt * 4 + dc) * 32 + lane) * 8);
                mma16816(s[nt], (const uint32_t*)&qh[dc], kb.x, kb.y);
                mma16816(s[nt], (const uint32_t*)&ql[dc], kb.x, kb.y);
            }
        }

        // Causal mask (diagonal tile only)
        if (kt == qt) {
            int r0 = w * 16 + (lane >> 2);
            int c0 = (lane & 3) << 1;
#pragma unroll
            for (int nt = 0; nt < 8; nt++) {
                int col = nt * 8 + c0;
                if (col > r0)         s[nt][0] = -1e30f;
                if (col + 1 > r0)     s[nt][1] = -1e30f;
                if (col > r0 + 8)     s[nt][2] = -1e30f;
                if (col + 1 > r0 + 8) s[nt][3] = -1e30f;
            }
        }

        // Online softmax per row-half
#pragma unroll
        for (int i = 0; i < 2; i++) {
            float tm = -1e30f;
#pragma unroll
            for (int nt = 0; nt < 8; nt++)
                tm = fmaxf(tm, fmaxf(s[nt][2 * i], s[nt][2 * i + 1]));
            tm = fmaxf(tm, __shfl_xor_sync(0xffffffffu, tm, 1));
            tm = fmaxf(tm, __shfl_xor_sync(0xffffffffu, tm, 2));
            float newm = fmaxf(m[i], tm);
            float fac  = __expf(m[i] - newm);
            m[i] = newm;
            float rs = 0.f;
#pragma unroll
            for (int nt = 0; nt < 8; nt++) {
                float p0 = __expf(s[nt][2 * i] - newm);
                float p1 = __expf(s[nt][2 * i + 1] - newm);
                s[nt][2 * i] = p0;
                s[nt][2 * i + 1] = p1;
                rs += p0 + p1;
            }
            rs += __shfl_xor_sync(0xffffffffu, rs, 1);
            rs += __shfl_xor_sync(0xffffffffu, rs, 2);
            l[i] = l[i] * fac + rs;
#pragma unroll
            for (int dt = 0; dt < 8; dt++) {
                o[dt][2 * i]     *= fac;
                o[dt][2 * i + 1] *= fac;
            }
        }

        // O += P @ V  (P single fp16)
#pragma unroll
        for (int t = 0; t < 4; t++) {
            uint32_t ph[4];
            ph[0] = packh(s[2*t][0],   s[2*t][1]);
            ph[1] = packh(s[2*t][2],   s[2*t][3]);
            ph[2] = packh(s[2*t+1][0], s[2*t+1][1]);
            ph[3] = packh(s[2*t+1][2], s[2*t+1][3]);
#pragma unroll
            for (int dt = 0; dt < 8; dt++) {
                uint2 v = *(const uint2*)(stV + ((dt * 4 + t) * 32 + lane) * 8);
                mma16816(o[dt], ph, v.x, v.y);
            }
        }
    }

    // Epilogue: normalize, write y A-fragments (single fp16) for proj GEMM
    const float inv0 = 1.f / l[0];
    const float inv1 = 1.f / l[1];
    const int mtg = b * 64 + qt * 4 + w;
#pragma unroll
    for (int dtc = 0; dtc < 4; dtc++) {
        uint4 hh;
        hh.x = packh(o[2*dtc][0]   * inv0, o[2*dtc][1]   * inv0);
        hh.y = packh(o[2*dtc][2]   * inv1, o[2*dtc][3]   * inv1);
        hh.z = packh(o[2*dtc+1][0] * inv0, o[2*dtc+1][1] * inv0);
        hh.w = packh(o[2*dtc+1][2] * inv1, o[2*dtc+1][3] * inv1);
        size_t idx = ((size_t)mtg * KT + h * 4 + dtc) * 32 + lane;
        g_yfh[idx] = hh;
    }
}

// ---------------------------------------------------------------------------
extern "C" void kernel_launch(void* const* d_in, const int* in_sizes, int n_in,
                              void* d_out, int out_size)
{
    const float* x  = (const float*)d_in[0];
    const float* Wq = (const float*)d_in[1];
    const float* bq = (const float*)d_in[2];
    const float* Wk = (const float*)d_in[3];
    const float* bk = (const float*)d_in[4];
    const float* Wv = (const float*)d_in[5];
    const float* bv = (const float*)d_in[6];
    const float* Wp = (const float*)d_in[7];
    const float* bp = (const float*)d_in[8];
    float* out = (float*)d_out;

    cudaFuncSetAttribute(qkv_mma, cudaFuncAttributeMaxDynamicSharedMemorySize, GEMM_SMEM);
    cudaFuncSetAttribute(proj_mma, cudaFuncAttributeMaxDynamicSharedMemorySize, GEMM_SMEM);
    cudaFuncSetAttribute(attn_mma, cudaFuncAttributeMaxDynamicSharedMemorySize, ATT_SMEM);

    split_xw_kernel<<<ACT_BLKS + W_BLKS, 256>>>(x, Wq, Wk, Wv, Wp);
    qkv_mma<<<dim3(Cn / 128, Mn / 128, 3), 256, GEMM_SMEM>>>(bq, bk, bv);
    attn_mma<<<dim3(Tn / 64, Hn, Bn), 128, ATT_SMEM>>>();
    proj_mma<<<dim3(Cn / 128, Mn / 128, 1), 256, GEMM_SMEM>>>(bp, out);
}

// round 10
// speedup vs baseline: 1.6251x; 1.2670x over previous
#include <cuda_runtime.h>
#include <cuda_fp16.h>
#include <cstdint>

static constexpr int Bn = 8, Tn = 1024, Cn = 768, Hn = 12, Dn = 64;
static constexpr int Mn = Bn * Tn;      // 8192
static constexpr int KT = Cn / 16;      // 48 k16 chunks
static constexpr int MT = Mn / 16;      // 512 m16 tiles
static constexpr int NTW = Cn / 8;      // 96 n8 tiles per weight matrix
static constexpr int BH = Bn * Hn;      // 96

// ---------------------------------------------------------------------------
// Scratch device globals
// ---------------------------------------------------------------------------
// A fragments (single fp16): [mt][tk][lane] -> uint4 (a0..a3)
__device__ uint4 g_xfh[MT * KT * 32];
__device__ uint4 g_yfh[MT * KT * 32];
// Weights B-frags (single fp16): [mat][nt][tk][lane] -> uint2 {b0,b1}
__device__ uint2 g_wf[4 * NTW * KT * 32];
// Q A-frags (hi/lo, pre-scaled 1/8): [bh][mt(64)][dc(4)][lane]
__device__ uint4 g_qfh[BH * 64 * 4 * 32];
__device__ uint4 g_qfl[BH * 64 * 4 * 32];
// K B-frags (single): [bh][nt(128)][dc(4)][lane]
__device__ uint2 g_kf[BH * 128 * 4 * 32];
// V^T B-frags (single): [bh][dt(8)][kc(64)][lane]
__device__ uint2 g_vtf[BH * 8 * 64 * 32];

// ---------------------------------------------------------------------------
// Helpers
// ---------------------------------------------------------------------------
__device__ __forceinline__ uint32_t smem_u32(const void* p) {
    uint32_t a;
    asm("{ .reg .u64 t; cvta.to.shared.u64 t, %1; cvt.u32.u64 %0, t; }"
        : "=r"(a) : "l"(p));
    return a;
}
__device__ __forceinline__ void cp16(uint32_t dst, const void* src) {
    asm volatile("cp.async.ca.shared.global [%0], [%1], 16;\n" :: "r"(dst), "l"(src));
}
__device__ __forceinline__ void cp8(uint32_t dst, const void* src) {
    asm volatile("cp.async.ca.shared.global [%0], [%1], 8;\n" :: "r"(dst), "l"(src));
}
#define CP_COMMIT() asm volatile("cp.async.commit_group;\n" ::: "memory")
#define CP_WAIT2()  asm volatile("cp.async.wait_group 2;\n" ::: "memory")
#define CP_WAIT1()  asm volatile("cp.async.wait_group 1;\n" ::: "memory")

__device__ __forceinline__ void mma16816(float* d, const uint32_t* a,
                                         uint32_t b0, uint32_t b1) {
    asm volatile(
        "mma.sync.aligned.m16n8k16.row.col.f32.f16.f16.f32 "
        "{%0,%1,%2,%3}, {%4,%5,%6,%7}, {%8,%9}, {%0,%1,%2,%3};\n"
        : "+f"(d[0]), "+f"(d[1]), "+f"(d[2]), "+f"(d[3])
        : "r"(a[0]), "r"(a[1]), "r"(a[2]), "r"(a[3]), "r"(b0), "r"(b1));
}

__device__ __forceinline__ uint32_t packh(float x, float y) {
    __half2 h = __floats2half2_rn(x, y);
    return *reinterpret_cast<uint32_t*>(&h);
}
__device__ __forceinline__ void split2h(float x, float y, uint32_t& h, uint32_t& l) {
    __half hx = __float2half_rn(x), hy = __float2half_rn(y);
    h = ((uint32_t)__half_as_ushort(hy) << 16) | (uint32_t)__half_as_ushort(hx);
    l = packh(x - __half2float(hx), y - __half2float(hy));
}

// ---------------------------------------------------------------------------
// Combined input split: x -> single fp16 A-frags; W -> single fp16 B-frags
// ---------------------------------------------------------------------------
static constexpr int ACT_BLKS = (MT * KT) / 8;          // 3072
static constexpr int W_BLKS   = (4 * NTW * KT) / 8;     // 2304

__global__ __launch_bounds__(256)
void split_xw_kernel(const float* __restrict__ X,
                     const float* __restrict__ Wq, const float* __restrict__ Wk,
                     const float* __restrict__ Wv, const float* __restrict__ Wp)
{
    int lane = threadIdx.x & 31;
    if (blockIdx.x < ACT_BLKS) {
        int w = (blockIdx.x * 256 + threadIdx.x) >> 5;
        int tm = w / KT, tk = w % KT;
        int row = tm * 16 + (lane >> 2);
        int kc  = tk * 16 + ((lane & 3) << 1);

        float2 v00 = *(const float2*)(X + (size_t)row * Cn + kc);
        float2 v10 = *(const float2*)(X + (size_t)(row + 8) * Cn + kc);
        float2 v01 = *(const float2*)(X + (size_t)row * Cn + kc + 8);
        float2 v11 = *(const float2*)(X + (size_t)(row + 8) * Cn + kc + 8);

        uint4 h;
        h.x = packh(v00.x, v00.y);
        h.y = packh(v10.x, v10.y);
        h.z = packh(v01.x, v01.y);
        h.w = packh(v11.x, v11.y);
        g_xfh[(size_t)w * 32 + lane] = h;
    } else {
        int w = ((blockIdx.x - ACT_BLKS) * 256 + threadIdx.x) >> 5;
        int mat = w / (NTW * KT);
        int rem = w % (NTW * KT);
        int tn = rem / KT, tk = rem % KT;

        const float* W;
        switch (mat) {
            case 0: W = Wq; break;
            case 1: W = Wk; break;
            case 2: W = Wv; break;
            default: W = Wp; break;
        }
        int n  = tn * 8 + (lane >> 2);
        int k0 = tk * 16 + ((lane & 3) << 1);

        uint2 o;
        o.x = packh(W[(size_t)k0 * Cn + n], W[(size_t)(k0 + 1) * Cn + n]);
        o.y = packh(W[(size_t)(k0 + 8) * Cn + n], W[(size_t)(k0 + 9) * Cn + n]);
        g_wf[(size_t)w * 32 + lane] = o;
    }
}

// ---------------------------------------------------------------------------
// fp16 tensor-core GEMM (single-A): Out tile = A[128,768] @ W[768,128] + bias
// 256 threads (8 warps: 4m x 2n). 4-stage cp.async pipeline, 8KB/stage.
// Stage layout: A [0,4K) mt*512+lane*16, B [4K,8K) nt*256+lane*8.
// Epilogue modes: 0 = fp32 (+bias) to Out; 1 = Q A-frags (hi/lo);
//                 2 = K B-frags; 3 = V^T B-frags via smem fp16 transpose.
// ---------------------------------------------------------------------------
static constexpr int STG_BYTES = 8192;
static constexpr int GEMM_SMEM = 40960;  // 4 stages (32KB) + headroom for V^T (34816B needed)

__device__ __forceinline__ void gemm_mma_body(const uint4* __restrict__ Ah,
                                              const uint2* __restrict__ Wf,
                                              const float* __restrict__ bias,
                                              float* __restrict__ Out,
                                              int mode)
{
    extern __shared__ __align__(16) char smem[];
    const uint32_t sbase = smem_u32(smem);
    const int tid  = threadIdx.x;
    const int lane = tid & 31;
    const int wid  = tid >> 5;
    const int wm   = wid >> 1;
    const int wn   = wid & 1;

    const int mtBase = blockIdx.y * 8;
    const int ntBase = blockIdx.x * 16;
    const int cp_t   = wid;

    const uint4* srcAh = Ah + ((size_t)(mtBase + cp_t) * KT) * 32 + lane;
    const uint2* srcB0 = Wf + ((size_t)(ntBase + cp_t) * KT) * 32 + lane;
    const uint2* srcB1 = Wf + ((size_t)(ntBase + cp_t + 8) * KT) * 32 + lane;

    const uint32_t dA0 = sbase + cp_t * 512 + lane * 16;
    const uint32_t dB0 = sbase + 4096 + cp_t * 256 + lane * 8;
    const uint32_t dB1 = dB0 + 2048;

    float d[2][8][4];
#pragma unroll
    for (int i = 0; i < 2; i++)
#pragma unroll
        for (int j = 0; j < 8; j++)
#pragma unroll
            for (int e = 0; e < 4; e++) d[i][j][e] = 0.f;

    auto issue = [&](int slot, int tk) {
        uint32_t so = (uint32_t)slot * STG_BYTES;
        cp16(dA0 + so, srcAh + (size_t)tk * 32);
        cp8(dB0 + so, srcB0 + (size_t)tk * 32);
        cp8(dB1 + so, srcB1 + (size_t)tk * 32);
    };

    issue(0, 0); CP_COMMIT();
    issue(1, 1); CP_COMMIT();
    issue(2, 2); CP_COMMIT();

    for (int k = 0; k < KT; k++) {
        CP_WAIT2();
        __syncthreads();
        if (k + 3 < KT) issue((k + 3) & 3, k + 3);
        CP_COMMIT();

        const char* stg = smem + (size_t)(k & 3) * STG_BYTES;
        uint4 ah0 = *(const uint4*)(stg + (wm * 2 + 0) * 512 + lane * 16);
        uint4 ah1 = *(const uint4*)(stg + (wm * 2 + 1) * 512 + lane * 16);
#pragma unroll
        for (int nt = 0; nt < 8; nt++) {
            uint2 b = *(const uint2*)(stg + 4096 + (wn * 8 + nt) * 256 + lane * 8);
            mma16816(d[0][nt], (const uint32_t*)&ah0, b.x, b.y);
            mma16816(d[1][nt], (const uint32_t*)&ah1, b.x, b.y);
        }
    }

    const int cb = blockIdx.x * 128 + wn * 64 + ((lane & 3) << 1);
    const int h  = blockIdx.x * 2 + wn;

    if (mode == 3) {
        // V^T fragments via smem fp16 transpose (row stride 136 halves).
        __syncthreads();
        __half* sv = reinterpret_cast<__half*>(smem);
#pragma unroll
        for (int mt = 0; mt < 2; mt++) {
            int r = wm * 32 + mt * 16 + (lane >> 2);
#pragma unroll
            for (int nt = 0; nt < 8; nt++) {
                int cl  = wn * 64 + nt * 8 + ((lane & 3) << 1);
                int col = blockIdx.x * 128 + cl;
                float bx = bias[col], by = bias[col + 1];
                *(__half2*)&sv[r * 136 + cl] =
                    __floats2half2_rn(d[mt][nt][0] + bx, d[mt][nt][1] + by);
                *(__half2*)&sv[(r + 8) * 136 + cl] =
                    __floats2half2_rn(d[mt][nt][2] + bx, d[mt][nt][3] + by);
            }
        }
        __syncthreads();
        const ushort* su = reinterpret_cast<const ushort*>(sv);
        const int bb  = blockIdx.y >> 3;
        const int kcb = (blockIdx.y & 7) * 8;
        const int dt  = wid;
#pragma unroll
        for (int hh = 0; hh < 2; hh++) {
            int dl  = hh * 64 + dt * 8 + (lane >> 2);
            int bh2 = bb * Hn + blockIdx.x * 2 + hh;
#pragma unroll
            for (int kl = 0; kl < 8; kl++) {
                int k0 = kl * 16 + ((lane & 3) << 1);
                uint2 o;
                o.x = (uint32_t)su[k0 * 136 + dl] |
                      ((uint32_t)su[(k0 + 1) * 136 + dl] << 16);
                o.y = (uint32_t)su[(k0 + 8) * 136 + dl] |
                      ((uint32_t)su[(k0 + 9) * 136 + dl] << 16);
                g_vtf[(((size_t)bh2 * 8 + dt) * 64 + kcb + kl) * 32 + lane] = o;
            }
        }
        return;
    }

#pragma unroll
    for (int mt = 0; mt < 2; mt++) {
        const int rg = blockIdx.y * 128 + wm * 32 + mt * 16;
        if (mode == 0) {
            const int r0 = rg + (lane >> 2);
#pragma unroll
            for (int nt = 0; nt < 8; nt++) {
                int col = cb + nt * 8;
                float bx = bias[col], by = bias[col + 1];
                *(float2*)(Out + (size_t)r0 * Cn + col) =
                    make_float2(d[mt][nt][0] + bx, d[mt][nt][1] + by);
                *(float2*)(Out + (size_t)(r0 + 8) * Cn + col) =
                    make_float2(d[mt][nt][2] + bx, d[mt][nt][3] + by);
            }
        } else if (mode == 1) {
            // Q A-fragments: scale 1/8, bias folded (hi/lo split kept)
            const int bq_ = rg >> 10;
            const int mtq = (rg & 1023) >> 4;
            const size_t base =
                ((size_t)((bq_ * Hn + h) * 64 + mtq) * 4) * 32 + lane;
#pragma unroll
            for (int dc = 0; dc < 4; dc++) {
                int c0 = cb + (2 * dc) * 8, c1 = cb + (2 * dc + 1) * 8;
                float b00 = bias[c0], b01 = bias[c0 + 1];
                float b10 = bias[c1], b11 = bias[c1 + 1];
                uint4 hh, ll;
                split2h((d[mt][2*dc][0]   + b00) * 0.125f,
                        (d[mt][2*dc][1]   + b01) * 0.125f, hh.x, ll.x);
                split2h((d[mt][2*dc][2]   + b00) * 0.125f,
                        (d[mt][2*dc][3]   + b01) * 0.125f, hh.y, ll.y);
                split2h((d[mt][2*dc+1][0] + b10) * 0.125f,
                        (d[mt][2*dc+1][1] + b11) * 0.125f, hh.z, ll.z);
                split2h((d[mt][2*dc+1][2] + b10) * 0.125f,
                        (d[mt][2*dc+1][3] + b11) * 0.125f, hh.w, ll.w);
                g_qfh[base + dc * 32] = hh;
                g_qfl[base + dc * 32] = ll;
            }
        } else {
            // K B-fragments (single fp16): two n8 key-tiles per m16
            const int bq_ = rg >> 10;
            const int ntk = (rg & 1023) >> 3;
            const size_t base =
                ((size_t)((bq_ * Hn + h) * 128 + ntk) * 4) * 32 + lane;
#pragma unroll
            for (int dc = 0; dc < 4; dc++) {
                int c0 = cb + (2 * dc) * 8, c1 = cb + (2 * dc + 1) * 8;
                float b00 = bias[c0], b01 = bias[c0 + 1];
                float b10 = bias[c1], b11 = bias[c1 + 1];
                uint2 t0, t1;
                t0.x = packh(d[mt][2*dc][0]   + b00, d[mt][2*dc][1]   + b01);
                t0.y = packh(d[mt][2*dc+1][0] + b10, d[mt][2*dc+1][1] + b11);
                t1.x = packh(d[mt][2*dc][2]   + b00, d[mt][2*dc][3]   + b01);
                t1.y = packh(d[mt][2*dc+1][2] + b10, d[mt][2*dc+1][3] + b11);
                g_kf[base + dc * 32]          = t0;
                g_kf[base + 4 * 32 + dc * 32] = t1;
            }
        }
    }
}

__global__ __launch_bounds__(256, 2)
void qkv_mma(const float* __restrict__ bq, const float* __restrict__ bk,
             const float* __restrict__ bv)
{
    const uint2* Wf = g_wf + (size_t)blockIdx.z * NTW * KT * 32;
    if (blockIdx.z == 0)      gemm_mma_body(g_xfh, Wf, bq, nullptr, 1);
    else if (blockIdx.z == 1) gemm_mma_body(g_xfh, Wf, bk, nullptr, 2);
    else                      gemm_mma_body(g_xfh, Wf, bv, nullptr, 3);
}

__global__ __launch_bounds__(256, 2)
void proj_mma(const float* __restrict__ bp, float* __restrict__ out)
{
    gemm_mma_body(g_yfh, g_wf + (size_t)3 * NTW * KT * 32, bp, out, 0);
}

// ---------------------------------------------------------------------------
// fp16 tensor-core flash attention (unchanged from R9).
// Block = (64 q-rows, head, batch), 128 threads = 4 warps (m16 each).
// CTA order reversed so the longest q-tiles launch first.
// ---------------------------------------------------------------------------
static constexpr int ATT_STG  = 16384;
static constexpr int ATT_SMEM = 3 * ATT_STG;   // 48KB

__global__ __launch_bounds__(128, 1)
void attn_mma()
{
    extern __shared__ __align__(16) char smem[];
    const uint32_t sbase = smem_u32(smem);
    const int tid  = threadIdx.x;
    const int lane = tid & 31;
    const int w    = tid >> 5;
    const int qt   = gridDim.x - 1 - blockIdx.x;
    const int h    = blockIdx.y;
    const int b    = blockIdx.z;
    const int bh   = b * Hn + h;
    const int nkt  = qt + 1;

    uint4 qh[4], ql[4];
    {
        const uint4* Qh = g_qfh + ((size_t)(bh * 64 + qt * 4 + w) * 4) * 32 + lane;
        const uint4* Ql = g_qfl + ((size_t)(bh * 64 + qt * 4 + w) * 4) * 32 + lane;
#pragma unroll
        for (int dc = 0; dc < 4; dc++) { qh[dc] = Qh[dc * 32]; ql[dc] = Ql[dc * 32]; }
    }

    float o[8][4];
#pragma unroll
    for (int i = 0; i < 8; i++)
#pragma unroll
        for (int j = 0; j < 4; j++) o[i][j] = 0.f;
    float m[2] = {-1e30f, -1e30f}, l[2] = {0.f, 0.f};

    const uint2* Ksrc = g_kf  + (size_t)bh * 128 * 4 * 32;
    const uint2* Vsrc = g_vtf + (size_t)bh * 8 * 64 * 32;
    const int vkc = w;

    auto issue = [&](int slot, int kt) {
        uint32_t so = sbase + (uint32_t)slot * ATT_STG;
        const uint2* ks = Ksrc + (size_t)kt * 1024;
#pragma unroll
        for (int i = 0; i < 8; i++)
            cp8(so + (uint32_t)(i * 128 + tid) * 8, ks + i * 128 + tid);
#pragma unroll
        for (int dt = 0; dt < 8; dt++)
            cp8(so + 8192 + (uint32_t)((dt * 4 + vkc) * 32 + lane) * 8,
                Vsrc + ((size_t)dt * 64 + kt * 4 + vkc) * 32 + lane);
    };

    issue(0, 0); CP_COMMIT();
    if (nkt > 1) issue(1, 1);
    CP_COMMIT();

    for (int kt = 0; kt < nkt; kt++) {
        CP_WAIT1();
        __syncthreads();
        if (kt + 2 < nkt) issue((kt + 2) % 3, kt + 2);
        CP_COMMIT();

        const char* stK = smem + (size_t)(kt % 3) * ATT_STG;
        const char* stV = stK + 8192;

        // S = Q @ K^T (Q split hi/lo, K single)
        float s[8][4];
#pragma unroll
        for (int i = 0; i < 8; i++)
#pragma unroll
            for (int j = 0; j < 4; j++) s[i][j] = 0.f;
#pragma unroll
        for (int dc = 0; dc < 4; dc++) {
#pragma unroll
            for (int nt = 0; nt < 8; nt++) {
                uint2 kb = *(const uint2*)(stK + ((nt * 4 + dc) * 32 + lane) * 8);
                mma16816(s[nt], (const uint32_t*)&qh[dc], kb.x, kb.y);
                mma16816(s[nt], (const uint32_t*)&ql[dc], kb.x, kb.y);
            }
        }

        // Causal mask (diagonal tile only)
        if (kt == qt) {
            int r0 = w * 16 + (lane >> 2);
            int c0 = (lane & 3) << 1;
#pragma unroll
            for (int nt = 0; nt < 8; nt++) {
                int col = nt * 8 + c0;
                if (col > r0)         s[nt][0] = -1e30f;
                if (col + 1 > r0)     s[nt][1] = -1e30f;
                if (col > r0 + 8)     s[nt][2] = -1e30f;
                if (col + 1 > r0 + 8) s[nt][3] = -1e30f;
            }
        }

        // Online softmax per row-half
#pragma unroll
        for (int i = 0; i < 2; i++) {
            float tm = -1e30f;
#pragma unroll
            for (int nt = 0; nt < 8; nt++)
                tm = fmaxf(tm, fmaxf(s[nt][2 * i], s[nt][2 * i + 1]));
            tm = fmaxf(tm, __shfl_xor_sync(0xffffffffu, tm, 1));
            tm = fmaxf(tm, __shfl_xor_sync(0xffffffffu, tm, 2));
            float newm = fmaxf(m[i], tm);
            float fac  = __expf(m[i] - newm);
            m[i] = newm;
            float rs = 0.f;
#pragma unroll
            for (int nt = 0; nt < 8; nt++) {
                float p0 = __expf(s[nt][2 * i] - newm);
                float p1 = __expf(s[nt][2 * i + 1] - newm);
                s[nt][2 * i] = p0;
                s[nt][2 * i + 1] = p1;
                rs += p0 + p1;
            }
            rs += __shfl_xor_sync(0xffffffffu, rs, 1);
            rs += __shfl_xor_sync(0xffffffffu, rs, 2);
            l[i] = l[i] * fac + rs;
#pragma unroll
            for (int dt = 0; dt < 8; dt++) {
                o[dt][2 * i]     *= fac;
                o[dt][2 * i + 1] *= fac;
            }
        }

        // O += P @ V  (P single fp16)
#pragma unroll
        for (int t = 0; t < 4; t++) {
            uint32_t ph[4];
            ph[0] = packh(s[2*t][0],   s[2*t][1]);
            ph[1] = packh(s[2*t][2],   s[2*t][3]);
            ph[2] = packh(s[2*t+1][0], s[2*t+1][1]);
            ph[3] = packh(s[2*t+1][2], s[2*t+1][3]);
#pragma unroll
            for (int dt = 0; dt < 8; dt++) {
                uint2 v = *(const uint2*)(stV + ((dt * 4 + t) * 32 + lane) * 8);
                mma16816(o[dt], ph, v.x, v.y);
            }
        }
    }

    // Epilogue: normalize, write y A-fragments (single fp16) for proj GEMM
    const float inv0 = 1.f / l[0];
    const float inv1 = 1.f / l[1];
    const int mtg = b * 64 + qt * 4 + w;
#pragma unroll
    for (int dtc = 0; dtc < 4; dtc++) {
        uint4 hh;
        hh.x = packh(o[2*dtc][0]   * inv0, o[2*dtc][1]   * inv0);
        hh.y = packh(o[2*dtc][2]   * inv1, o[2*dtc][3]   * inv1);
        hh.z = packh(o[2*dtc+1][0] * inv0, o[2*dtc+1][1] * inv0);
        hh.w = packh(o[2*dtc+1][2] * inv1, o[2*dtc+1][3] * inv1);
        size_t idx = ((size_t)mtg * KT + h * 4 + dtc) * 32 + lane;
        g_yfh[idx] = hh;
    }
}

// ---------------------------------------------------------------------------
extern "C" void kernel_launch(void* const* d_in, const int* in_sizes, int n_in,
                              void* d_out, int out_size)
{
    const float* x  = (const float*)d_in[0];
    const float* Wq = (const float*)d_in[1];
    const float* bq = (const float*)d_in[2];
    const float* Wk = (const float*)d_in[3];
    const float* bk = (const float*)d_in[4];
    const float* Wv = (const float*)d_in[5];
    const float* bv = (const float*)d_in[6];
    const float* Wp = (const float*)d_in[7];
    const float* bp = (const float*)d_in[8];
    float* out = (float*)d_out;

    cudaFuncSetAttribute(qkv_mma, cudaFuncAttributeMaxDynamicSharedMemorySize, GEMM_SMEM);
    cudaFuncSetAttribute(proj_mma, cudaFuncAttributeMaxDynamicSharedMemorySize, GEMM_SMEM);
    cudaFuncSetAttribute(attn_mma, cudaFuncAttributeMaxDynamicSharedMemorySize, ATT_SMEM);

    split_xw_kernel<<<ACT_BLKS + W_BLKS, 256>>>(x, Wq, Wk, Wv, Wp);
    qkv_mma<<<dim3(Cn / 128, Mn / 128, 3), 256, GEMM_SMEM>>>(bq, bk, bv);
    attn_mma<<<dim3(Tn / 64, Hn, Bn), 128, ATT_SMEM>>>();
    proj_mma<<<dim3(Cn / 128, Mn / 128, 1), 256, GEMM_SMEM>>>(bp, out);
}

// round 11
// speedup vs baseline: 1.7226x; 1.0600x over previous
#include <cuda_runtime.h>
#include <cuda_fp16.h>
#include <cstdint>

static constexpr int Bn = 8, Tn = 1024, Cn = 768, Hn = 12, Dn = 64;
static constexpr int Mn = Bn * Tn;      // 8192
static constexpr int KT = Cn / 16;      // 48 k16 chunks
static constexpr int MT = Mn / 16;      // 512 m16 tiles
static constexpr int NTW = Cn / 8;      // 96 n8 tiles per weight matrix
static constexpr int BH = Bn * Hn;      // 96

// ---------------------------------------------------------------------------
// Scratch device globals
// ---------------------------------------------------------------------------
// A fragments (single fp16): [mt][tk][lane] -> uint4 (a0..a3)
__device__ uint4 g_xfh[MT * KT * 32];
__device__ uint4 g_yfh[MT * KT * 32];
// Weights B-frags (single fp16): [mat][nt][tk][lane] -> uint2 {b0,b1}
__device__ uint2 g_wf[4 * NTW * KT * 32];
// Q A-frags (single fp16, pre-scaled 1/8): [bh][mt(64)][dc(4)][lane]
__device__ uint4 g_qfh[BH * 64 * 4 * 32];
// K B-frags (single): [bh][nt(128)][dc(4)][lane]
__device__ uint2 g_kf[BH * 128 * 4 * 32];
// V^T B-frags (single): [bh][dt(8)][kc(64)][lane]
__device__ uint2 g_vtf[BH * 8 * 64 * 32];

// ---------------------------------------------------------------------------
// Helpers
// ---------------------------------------------------------------------------
__device__ __forceinline__ uint32_t smem_u32(const void* p) {
    uint32_t a;
    asm("{ .reg .u64 t; cvta.to.shared.u64 t, %1; cvt.u32.u64 %0, t; }"
        : "=r"(a) : "l"(p));
    return a;
}
__device__ __forceinline__ void cp16(uint32_t dst, const void* src) {
    asm volatile("cp.async.ca.shared.global [%0], [%1], 16;\n" :: "r"(dst), "l"(src));
}
__device__ __forceinline__ void cp8(uint32_t dst, const void* src) {
    asm volatile("cp.async.ca.shared.global [%0], [%1], 8;\n" :: "r"(dst), "l"(src));
}
#define CP_COMMIT() asm volatile("cp.async.commit_group;\n" ::: "memory")
#define CP_WAIT2()  asm volatile("cp.async.wait_group 2;\n" ::: "memory")
#define CP_WAIT1()  asm volatile("cp.async.wait_group 1;\n" ::: "memory")

__device__ __forceinline__ void mma16816(float* d, const uint32_t* a,
                                         uint32_t b0, uint32_t b1) {
    asm volatile(
        "mma.sync.aligned.m16n8k16.row.col.f32.f16.f16.f32 "
        "{%0,%1,%2,%3}, {%4,%5,%6,%7}, {%8,%9}, {%0,%1,%2,%3};\n"
        : "+f"(d[0]), "+f"(d[1]), "+f"(d[2]), "+f"(d[3])
        : "r"(a[0]), "r"(a[1]), "r"(a[2]), "r"(a[3]), "r"(b0), "r"(b1));
}

__device__ __forceinline__ uint32_t packh(float x, float y) {
    __half2 h = __floats2half2_rn(x, y);
    return *reinterpret_cast<uint32_t*>(&h);
}

// ---------------------------------------------------------------------------
// Combined input split: x -> single fp16 A-frags; W -> single fp16 B-frags
// ---------------------------------------------------------------------------
static constexpr int ACT_BLKS = (MT * KT) / 8;          // 3072
static constexpr int W_BLKS   = (4 * NTW * KT) / 8;     // 2304

__global__ __launch_bounds__(256)
void split_xw_kernel(const float* __restrict__ X,
                     const float* __restrict__ Wq, const float* __restrict__ Wk,
                     const float* __restrict__ Wv, const float* __restrict__ Wp)
{
    int lane = threadIdx.x & 31;
    if (blockIdx.x < ACT_BLKS) {
        int w = (blockIdx.x * 256 + threadIdx.x) >> 5;
        int tm = w / KT, tk = w % KT;
        int row = tm * 16 + (lane >> 2);
        int kc  = tk * 16 + ((lane & 3) << 1);

        float2 v00 = *(const float2*)(X + (size_t)row * Cn + kc);
        float2 v10 = *(const float2*)(X + (size_t)(row + 8) * Cn + kc);
        float2 v01 = *(const float2*)(X + (size_t)row * Cn + kc + 8);
        float2 v11 = *(const float2*)(X + (size_t)(row + 8) * Cn + kc + 8);

        uint4 h;
        h.x = packh(v00.x, v00.y);
        h.y = packh(v10.x, v10.y);
        h.z = packh(v01.x, v01.y);
        h.w = packh(v11.x, v11.y);
        g_xfh[(size_t)w * 32 + lane] = h;
    } else {
        int w = ((blockIdx.x - ACT_BLKS) * 256 + threadIdx.x) >> 5;
        int mat = w / (NTW * KT);
        int rem = w % (NTW * KT);
        int tn = rem / KT, tk = rem % KT;

        const float* W;
        switch (mat) {
            case 0: W = Wq; break;
            case 1: W = Wk; break;
            case 2: W = Wv; break;
            default: W = Wp; break;
        }
        int n  = tn * 8 + (lane >> 2);
        int k0 = tk * 16 + ((lane & 3) << 1);

        uint2 o;
        o.x = packh(W[(size_t)k0 * Cn + n], W[(size_t)(k0 + 1) * Cn + n]);
        o.y = packh(W[(size_t)(k0 + 8) * Cn + n], W[(size_t)(k0 + 9) * Cn + n]);
        g_wf[(size_t)w * 32 + lane] = o;
    }
}

// ---------------------------------------------------------------------------
// fp16 tensor-core GEMM (single-A): Out tile = A[128,768] @ W[768,128] + bias
// 256 threads (8 warps: 4m x 2n). 4-stage cp.async pipeline, 8KB/stage.
// Stage layout: A [0,4K) mt*512+lane*16, B [4K,8K) nt*256+lane*8.
// Epilogue modes: 0 = fp32 (+bias) to Out; 1 = Q A-frags (single fp16);
//                 2 = K B-frags; 3 = V^T B-frags via smem fp16 transpose.
// ---------------------------------------------------------------------------
static constexpr int STG_BYTES = 8192;
static constexpr int GEMM_SMEM = 40960;  // 4 stages (32KB) + V^T transpose headroom

__device__ __forceinline__ void gemm_mma_body(const uint4* __restrict__ Ah,
                                              const uint2* __restrict__ Wf,
                                              const float* __restrict__ bias,
                                              float* __restrict__ Out,
                                              int mode)
{
    extern __shared__ __align__(16) char smem[];
    const uint32_t sbase = smem_u32(smem);
    const int tid  = threadIdx.x;
    const int lane = tid & 31;
    const int wid  = tid >> 5;
    const int wm   = wid >> 1;
    const int wn   = wid & 1;

    const int mtBase = blockIdx.y * 8;
    const int ntBase = blockIdx.x * 16;
    const int cp_t   = wid;

    const uint4* srcAh = Ah + ((size_t)(mtBase + cp_t) * KT) * 32 + lane;
    const uint2* srcB0 = Wf + ((size_t)(ntBase + cp_t) * KT) * 32 + lane;
    const uint2* srcB1 = Wf + ((size_t)(ntBase + cp_t + 8) * KT) * 32 + lane;

    const uint32_t dA0 = sbase + cp_t * 512 + lane * 16;
    const uint32_t dB0 = sbase + 4096 + cp_t * 256 + lane * 8;
    const uint32_t dB1 = dB0 + 2048;

    float d[2][8][4];
#pragma unroll
    for (int i = 0; i < 2; i++)
#pragma unroll
        for (int j = 0; j < 8; j++)
#pragma unroll
            for (int e = 0; e < 4; e++) d[i][j][e] = 0.f;

    auto issue = [&](int slot, int tk) {
        uint32_t so = (uint32_t)slot * STG_BYTES;
        cp16(dA0 + so, srcAh + (size_t)tk * 32);
        cp8(dB0 + so, srcB0 + (size_t)tk * 32);
        cp8(dB1 + so, srcB1 + (size_t)tk * 32);
    };

    issue(0, 0); CP_COMMIT();
    issue(1, 1); CP_COMMIT();
    issue(2, 2); CP_COMMIT();

    for (int k = 0; k < KT; k++) {
        CP_WAIT2();
        __syncthreads();
        if (k + 3 < KT) issue((k + 3) & 3, k + 3);
        CP_COMMIT();

        const char* stg = smem + (size_t)(k & 3) * STG_BYTES;
        uint4 ah0 = *(const uint4*)(stg + (wm * 2 + 0) * 512 + lane * 16);
        uint4 ah1 = *(const uint4*)(stg + (wm * 2 + 1) * 512 + lane * 16);
#pragma unroll
        for (int nt = 0; nt < 8; nt++) {
            uint2 b = *(const uint2*)(stg + 4096 + (wn * 8 + nt) * 256 + lane * 8);
            mma16816(d[0][nt], (const uint32_t*)&ah0, b.x, b.y);
            mma16816(d[1][nt], (const uint32_t*)&ah1, b.x, b.y);
        }
    }

    const int cb = blockIdx.x * 128 + wn * 64 + ((lane & 3) << 1);
    const int h  = blockIdx.x * 2 + wn;

    if (mode == 3) {
        // V^T fragments via smem fp16 transpose (row stride 136 halves).
        __syncthreads();
        __half* sv = reinterpret_cast<__half*>(smem);
#pragma unroll
        for (int mt = 0; mt < 2; mt++) {
            int r = wm * 32 + mt * 16 + (lane >> 2);
#pragma unroll
            for (int nt = 0; nt < 8; nt++) {
                int cl  = wn * 64 + nt * 8 + ((lane & 3) << 1);
                int col = blockIdx.x * 128 + cl;
                float bx = bias[col], by = bias[col + 1];
                *(__half2*)&sv[r * 136 + cl] =
                    __floats2half2_rn(d[mt][nt][0] + bx, d[mt][nt][1] + by);
                *(__half2*)&sv[(r + 8) * 136 + cl] =
                    __floats2half2_rn(d[mt][nt][2] + bx, d[mt][nt][3] + by);
            }
        }
        __syncthreads();
        const ushort* su = reinterpret_cast<const ushort*>(sv);
        const int bb  = blockIdx.y >> 3;
        const int kcb = (blockIdx.y & 7) * 8;
        const int dt  = wid;
#pragma unroll
        for (int hh = 0; hh < 2; hh++) {
            int dl  = hh * 64 + dt * 8 + (lane >> 2);
            int bh2 = bb * Hn + blockIdx.x * 2 + hh;
#pragma unroll
            for (int kl = 0; kl < 8; kl++) {
                int k0 = kl * 16 + ((lane & 3) << 1);
                uint2 o;
                o.x = (uint32_t)su[k0 * 136 + dl] |
                      ((uint32_t)su[(k0 + 1) * 136 + dl] << 16);
                o.y = (uint32_t)su[(k0 + 8) * 136 + dl] |
                      ((uint32_t)su[(k0 + 9) * 136 + dl] << 16);
                g_vtf[(((size_t)bh2 * 8 + dt) * 64 + kcb + kl) * 32 + lane] = o;
            }
        }
        return;
    }

#pragma unroll
    for (int mt = 0; mt < 2; mt++) {
        const int rg = blockIdx.y * 128 + wm * 32 + mt * 16;
        if (mode == 0) {
            const int r0 = rg + (lane >> 2);
#pragma unroll
            for (int nt = 0; nt < 8; nt++) {
                int col = cb + nt * 8;
                float bx = bias[col], by = bias[col + 1];
                *(float2*)(Out + (size_t)r0 * Cn + col) =
                    make_float2(d[mt][nt][0] + bx, d[mt][nt][1] + by);
                *(float2*)(Out + (size_t)(r0 + 8) * Cn + col) =
                    make_float2(d[mt][nt][2] + bx, d[mt][nt][3] + by);
            }
        } else if (mode == 1) {
            // Q A-fragments (single fp16): scale 1/8, bias folded
            const int bq_ = rg >> 10;
            const int mtq = (rg & 1023) >> 4;
            const size_t base =
                ((size_t)((bq_ * Hn + h) * 64 + mtq) * 4) * 32 + lane;
#pragma unroll
            for (int dc = 0; dc < 4; dc++) {
                int c0 = cb + (2 * dc) * 8, c1 = cb + (2 * dc + 1) * 8;
                float b00 = bias[c0], b01 = bias[c0 + 1];
                float b10 = bias[c1], b11 = bias[c1 + 1];
                uint4 hh;
                hh.x = packh((d[mt][2*dc][0]   + b00) * 0.125f,
                             (d[mt][2*dc][1]   + b01) * 0.125f);
                hh.y = packh((d[mt][2*dc][2]   + b00) * 0.125f,
                             (d[mt][2*dc][3]   + b01) * 0.125f);
                hh.z = packh((d[mt][2*dc+1][0] + b10) * 0.125f,
                             (d[mt][2*dc+1][1] + b11) * 0.125f);
                hh.w = packh((d[mt][2*dc+1][2] + b10) * 0.125f,
                             (d[mt][2*dc+1][3] + b11) * 0.125f);
                g_qfh[base + dc * 32] = hh;
            }
        } else {
            // K B-fragments (single fp16): two n8 key-tiles per m16
            const int bq_ = rg >> 10;
            const int ntk = (rg & 1023) >> 3;
            const size_t base =
                ((size_t)((bq_ * Hn + h) * 128 + ntk) * 4) * 32 + lane;
#pragma unroll
            for (int dc = 0; dc < 4; dc++) {
                int c0 = cb + (2 * dc) * 8, c1 = cb + (2 * dc + 1) * 8;
                float b00 = bias[c0], b01 = bias[c0 + 1];
                float b10 = bias[c1], b11 = bias[c1 + 1];
                uint2 t0, t1;
                t0.x = packh(d[mt][2*dc][0]   + b00, d[mt][2*dc][1]   + b01);
                t0.y = packh(d[mt][2*dc+1][0] + b10, d[mt][2*dc+1][1] + b11);
                t1.x = packh(d[mt][2*dc][2]   + b00, d[mt][2*dc][3]   + b01);
                t1.y = packh(d[mt][2*dc+1][2] + b10, d[mt][2*dc+1][3] + b11);
                g_kf[base + dc * 32]          = t0;
                g_kf[base + 4 * 32 + dc * 32] = t1;
            }
        }
    }
}

__global__ __launch_bounds__(256, 2)
void qkv_mma(const float* __restrict__ bq, const float* __restrict__ bk,
             const float* __restrict__ bv)
{
    const uint2* Wf = g_wf + (size_t)blockIdx.z * NTW * KT * 32;
    if (blockIdx.z == 0)      gemm_mma_body(g_xfh, Wf, bq, nullptr, 1);
    else if (blockIdx.z == 1) gemm_mma_body(g_xfh, Wf, bk, nullptr, 2);
    else                      gemm_mma_body(g_xfh, Wf, bv, nullptr, 3);
}

__global__ __launch_bounds__(256, 2)
void proj_mma(const float* __restrict__ bp, float* __restrict__ out)
{
    gemm_mma_body(g_yfh, g_wf + (size_t)3 * NTW * KT * 32, bp, out, 0);
}

// ---------------------------------------------------------------------------
// fp16 tensor-core flash attention. Q single fp16 (1 MMA per S step).
// Block = (64 q-rows, head, batch), 128 threads = 4 warps (m16 each).
// CTA order reversed so the longest q-tiles launch first.
// ---------------------------------------------------------------------------
static constexpr int ATT_STG  = 16384;
static constexpr int ATT_SMEM = 3 * ATT_STG;   // 48KB

__global__ __launch_bounds__(128, 1)
void attn_mma()
{
    extern __shared__ __align__(16) char smem[];
    const uint32_t sbase = smem_u32(smem);
    const int tid  = threadIdx.x;
    const int lane = tid & 31;
    const int w    = tid >> 5;
    const int qt   = gridDim.x - 1 - blockIdx.x;
    const int h    = blockIdx.y;
    const int b    = blockIdx.z;
    const int bh   = b * Hn + h;
    const int nkt  = qt + 1;

    uint4 qh[4];
    {
        const uint4* Qh = g_qfh + ((size_t)(bh * 64 + qt * 4 + w) * 4) * 32 + lane;
#pragma unroll
        for (int dc = 0; dc < 4; dc++) qh[dc] = Qh[dc * 32];
    }

    float o[8][4];
#pragma unroll
    for (int i = 0; i < 8; i++)
#pragma unroll
        for (int j = 0; j < 4; j++) o[i][j] = 0.f;
    float m[2] = {-1e30f, -1e30f}, l[2] = {0.f, 0.f};

    const uint2* Ksrc = g_kf  + (size_t)bh * 128 * 4 * 32;
    const uint2* Vsrc = g_vtf + (size_t)bh * 8 * 64 * 32;
    const int vkc = w;

    auto issue = [&](int slot, int kt) {
        uint32_t so = sbase + (uint32_t)slot * ATT_STG;
        const uint2* ks = Ksrc + (size_t)kt * 1024;
#pragma unroll
        for (int i = 0; i < 8; i++)
            cp8(so + (uint32_t)(i * 128 + tid) * 8, ks + i * 128 + tid);
#pragma unroll
        for (int dt = 0; dt < 8; dt++)
            cp8(so + 8192 + (uint32_t)((dt * 4 + vkc) * 32 + lane) * 8,
                Vsrc + ((size_t)dt * 64 + kt * 4 + vkc) * 32 + lane);
    };

    issue(0, 0); CP_COMMIT();
    if (nkt > 1) issue(1, 1);
    CP_COMMIT();

    for (int kt = 0; kt < nkt; kt++) {
        CP_WAIT1();
        __syncthreads();
        if (kt + 2 < nkt) issue((kt + 2) % 3, kt + 2);
        CP_COMMIT();

        const char* stK = smem + (size_t)(kt % 3) * ATT_STG;
        const char* stV = stK + 8192;

        // S = Q @ K^T (both single fp16)
        float s[8][4];
#pragma unroll
        for (int i = 0; i < 8; i++)
#pragma unroll
            for (int j = 0; j < 4; j++) s[i][j] = 0.f;
#pragma unroll
        for (int dc = 0; dc < 4; dc++) {
#pragma unroll
            for (int nt = 0; nt < 8; nt++) {
                uint2 kb = *(const uint2*)(stK + ((nt * 4 + dc) * 32 + lane) * 8);
                mma16816(s[nt], (const uint32_t*)&qh[dc], kb.x, kb.y);
            }
        }

        // Causal mask (diagonal tile only)
        if (kt == qt) {
            int r0 = w * 16 + (lane >> 2);
            int c0 = (lane & 3) << 1;
#pragma unroll
            for (int nt = 0; nt < 8; nt++) {
                int col = nt * 8 + c0;
                if (col > r0)         s[nt][0] = -1e30f;
                if (col + 1 > r0)     s[nt][1] = -1e30f;
                if (col > r0 + 8)     s[nt][2] = -1e30f;
                if (col + 1 > r0 + 8) s[nt][3] = -1e30f;
            }
        }

        // Online softmax per row-half
#pragma unroll
        for (int i = 0; i < 2; i++) {
            float tm = -1e30f;
#pragma unroll
            for (int nt = 0; nt < 8; nt++)
                tm = fmaxf(tm, fmaxf(s[nt][2 * i], s[nt][2 * i + 1]));
            tm = fmaxf(tm, __shfl_xor_sync(0xffffffffu, tm, 1));
            tm = fmaxf(tm, __shfl_xor_sync(0xffffffffu, tm, 2));
            float newm = fmaxf(m[i], tm);
            float fac  = __expf(m[i] - newm);
            m[i] = newm;
            float rs = 0.f;
#pragma unroll
            for (int nt = 0; nt < 8; nt++) {
                float p0 = __expf(s[nt][2 * i] - newm);
                float p1 = __expf(s[nt][2 * i + 1] - newm);
                s[nt][2 * i] = p0;
                s[nt][2 * i + 1] = p1;
                rs += p0 + p1;
            }
            rs += __shfl_xor_sync(0xffffffffu, rs, 1);
            rs += __shfl_xor_sync(0xffffffffu, rs, 2);
            l[i] = l[i] * fac + rs;
#pragma unroll
            for (int dt = 0; dt < 8; dt++) {
                o[dt][2 * i]     *= fac;
                o[dt][2 * i + 1] *= fac;
            }
        }

        // O += P @ V  (P single fp16)
#pragma unroll
        for (int t = 0; t < 4; t++) {
            uint32_t ph[4];
            ph[0] = packh(s[2*t][0],   s[2*t][1]);
            ph[1] = packh(s[2*t][2],   s[2*t][3]);
            ph[2] = packh(s[2*t+1][0], s[2*t+1][1]);
            ph[3] = packh(s[2*t+1][2], s[2*t+1][3]);
#pragma unroll
            for (int dt = 0; dt < 8; dt++) {
                uint2 v = *(const uint2*)(stV + ((dt * 4 + t) * 32 + lane) * 8);
                mma16816(o[dt], ph, v.x, v.y);
            }
        }
    }

    // Epilogue: normalize, write y A-fragments (single fp16) for proj GEMM
    const float inv0 = 1.f / l[0];
    const float inv1 = 1.f / l[1];
    const int mtg = b * 64 + qt * 4 + w;
#pragma unroll
    for (int dtc = 0; dtc < 4; dtc++) {
        uint4 hh;
        hh.x = packh(o[2*dtc][0]   * inv0, o[2*dtc][1]   * inv0);
        hh.y = packh(o[2*dtc][2]   * inv1, o[2*dtc][3]   * inv1);
        hh.z = packh(o[2*dtc+1][0] * inv0, o[2*dtc+1][1] * inv0);
        hh.w = packh(o[2*dtc+1][2] * inv1, o[2*dtc+1][3] * inv1);
        size_t idx = ((size_t)mtg * KT + h * 4 + dtc) * 32 + lane;
        g_yfh[idx] = hh;
    }
}

// ---------------------------------------------------------------------------
extern "C" void kernel_launch(void* const* d_in, const int* in_sizes, int n_in,
                              void* d_out, int out_size)
{
    const float* x  = (const float*)d_in[0];
    const float* Wq = (const float*)d_in[1];
    const float* bq = (const float*)d_in[2];
    const float* Wk = (const float*)d_in[3];
    const float* bk = (const float*)d_in[4];
    const float* Wv = (const float*)d_in[5];
    const float* bv = (const float*)d_in[6];
    const float* Wp = (const float*)d_in[7];
    const float* bp = (const float*)d_in[8];
    float* out = (float*)d_out;

    cudaFuncSetAttribute(qkv_mma, cudaFuncAttributeMaxDynamicSharedMemorySize, GEMM_SMEM);
    cudaFuncSetAttribute(proj_mma, cudaFuncAttributeMaxDynamicSharedMemorySize, GEMM_SMEM);
    cudaFuncSetAttribute(attn_mma, cudaFuncAttributeMaxDynamicSharedMemorySize, ATT_SMEM);

    split_xw_kernel<<<ACT_BLKS + W_BLKS, 256>>>(x, Wq, Wk, Wv, Wp);
    qkv_mma<<<dim3(Cn / 128, Mn / 128, 3), 256, GEMM_SMEM>>>(bq, bk, bv);
    attn_mma<<<dim3(Tn / 64, Hn, Bn), 128, ATT_SMEM>>>();
    proj_mma<<<dim3(Cn / 128, Mn / 128, 1), 256, GEMM_SMEM>>>(bp, out);
}